// round 2
// baseline (speedup 1.0000x reference)
#include <cuda_runtime.h>

typedef unsigned long long ull;

#define B_SZ   2048
#define N_INST 8
#define N_FEAT 100
#define N_HID  40
#define NC     40
#define NM     41

#define BT     32      // batches per CTA
#define NTHR   160     // 2 c-groups x 80 threads (8 tb x 10 tg)

// Precomputed G[i,c] = A[i,c] @ Bp[i,c], both layouts. 2 x 5.12 MB, L2-resident.
__device__ float g_G [N_INST * NC * N_FEAT * N_HID];   // [ic][f][h]
__device__ float g_Gt[N_INST * NC * N_FEAT * N_HID];   // [ic][h][f]

// ---- packed fp32x2 helpers (Blackwell FFMA2 — PTX-only) ----
__device__ __forceinline__ ull ffma2(ull a, ull b, ull c) {
    ull d;
    asm("fma.rn.f32x2 %0, %1, %2, %3;" : "=l"(d) : "l"(a), "l"(b), "l"(c));
    return d;
}
__device__ __forceinline__ ull fmul2(ull a, ull b) {
    ull d;
    asm("mul.rn.f32x2 %0, %1, %2;" : "=l"(d) : "l"(a), "l"(b));
    return d;
}
__device__ __forceinline__ float2 unpk(ull v) {
    float2 r;
    asm("mov.b64 {%0, %1}, %2;" : "=f"(r.x), "=f"(r.y) : "l"(v));
    return r;
}

// ---------------------------------------------------------------------------
// Kernel 1: G[ic][f][h] = sum_m A[ic][f][m] * Bp[ic][m][h]  (+ transposed copy)
// ---------------------------------------------------------------------------
__global__ void compute_G_kernel(const float* __restrict__ A,
                                 const float* __restrict__ Bp) {
    __shared__ float As[N_FEAT * NM];
    __shared__ float Bs[NM * N_HID];
    const int ic = blockIdx.x;
    const float* Ap  = A  + (size_t)ic * N_FEAT * NM;
    const float* Bpp = Bp + (size_t)ic * NM * N_HID;
    for (int idx = threadIdx.x; idx < N_FEAT * NM; idx += blockDim.x) As[idx] = Ap[idx];
    for (int idx = threadIdx.x; idx < NM * N_HID; idx += blockDim.x) Bs[idx] = Bpp[idx];
    __syncthreads();
    for (int idx = threadIdx.x; idx < N_FEAT * N_HID; idx += blockDim.x) {
        const int f = idx / N_HID;
        const int h = idx % N_HID;
        float s = 0.f;
#pragma unroll
        for (int m = 0; m < NM; m++)
            s += As[f * NM + m] * Bs[m * N_HID + h];
        g_G [(size_t)ic * (N_FEAT * N_HID) + f * N_HID + h] = s;
        g_Gt[(size_t)ic * (N_FEAT * N_HID) + h * N_FEAT + f] = s;
    }
}

// ---------------------------------------------------------------------------
// Kernel 2: fused. No syncs in the c-loops; G/Gt streamed from L2.
// SMEM (floats):
//   xsD   [100][64]  6400   x duplicated: xsD[f][2b]=xsD[f][2b+1]=x[b][f]
//                           (aliased as out-partial scratch [32][100] in epilogue)
//   msD   [ 40][64]  2560   mask duplicated
//   hPart [2][40][32] 2560  per-c-group partial h
//   hTd   [ 40][64]  2560   merged h, duplicated
// total 14080 floats = 56320 B
// ---------------------------------------------------------------------------
__global__ __launch_bounds__(NTHR)
void tmsspd_main_kernel(const float* __restrict__ x,
                        const float* __restrict__ mask,
                        const float* __restrict__ bfin,
                        float* __restrict__ out) {
    extern __shared__ float sm[];
    float* xsD   = sm;            // 6400
    float* msD   = sm + 6400;     // 2560
    float* hPart = sm + 8960;     // 2560
    float* hTd   = sm + 11520;    // 2560

    const int i  = blockIdx.y;
    const int b0 = blockIdx.x * BT;
    const int t  = threadIdx.x;
    const int cg = t / 80;        // c-group: 0 -> c 0..19, 1 -> c 20..39
    const int tt = t % 80;
    const int tb = tt % 8;        // 4 batches each: b = tb*4 + 0..3
    const int tg = tt / 8;        // 0..9 : phase A h-group (4h) / phase B f-group (10f)
    const int c0 = cg * 20;

    // ---- load x (duplicated) ----
    for (int idx = t; idx < BT * N_FEAT; idx += NTHR) {
        const int bl = idx / N_FEAT;
        const int f  = idx % N_FEAT;
        const float v = x[((size_t)(b0 + bl) * N_INST + i) * N_FEAT + f];
        xsD[f * 64 + 2 * bl]     = v;
        xsD[f * 64 + 2 * bl + 1] = v;
    }
    // ---- load mask (duplicated) ----
    for (int idx = t; idx < BT * NC; idx += NTHR) {
        const int bl = idx / NC;
        const int c  = idx % NC;
        const float v = mask[((size_t)(b0 + bl) * N_INST + i) * NC + c];
        msD[c * 64 + 2 * bl]     = v;
        msD[c * 64 + 2 * bl + 1] = v;
    }
    __syncthreads();

    const float* Gbase  = g_G  + (size_t)i * NC * (N_FEAT * N_HID);
    const float* Gtbase = g_Gt + (size_t)i * NC * (N_FEAT * N_HID);

    // ================= Phase A: partial h over this cg's 20 c's ==============
    // acc pairs: [4 batches][2 h-pairs], packed over adjacent h
    ull hacc[4][2];
#pragma unroll
    for (int b = 0; b < 4; b++) { hacc[b][0] = 0ull; hacc[b][1] = 0ull; }

    for (int cc = 0; cc < 20; cc++) {
        const int c = c0 + cc;
        const float* Grow = Gbase + (size_t)c * (N_FEAT * N_HID);

        ull dot[4][2];
#pragma unroll
        for (int b = 0; b < 4; b++) { dot[b][0] = 0ull; dot[b][1] = 0ull; }

#pragma unroll 4
        for (int f = 0; f < N_FEAT; f++) {
            const ulonglong2 xa = *reinterpret_cast<const ulonglong2*>(&xsD[f * 64 + tb * 8]);
            const ulonglong2 xb = *reinterpret_cast<const ulonglong2*>(&xsD[f * 64 + tb * 8 + 4]);
            const ulonglong2 gg = *reinterpret_cast<const ulonglong2*>(&Grow[f * N_HID + tg * 4]);
            dot[0][0] = ffma2(xa.x, gg.x, dot[0][0]);
            dot[0][1] = ffma2(xa.x, gg.y, dot[0][1]);
            dot[1][0] = ffma2(xa.y, gg.x, dot[1][0]);
            dot[1][1] = ffma2(xa.y, gg.y, dot[1][1]);
            dot[2][0] = ffma2(xb.x, gg.x, dot[2][0]);
            dot[2][1] = ffma2(xb.x, gg.y, dot[2][1]);
            dot[3][0] = ffma2(xb.y, gg.x, dot[3][0]);
            dot[3][1] = ffma2(xb.y, gg.y, dot[3][1]);
        }

        const ulonglong2 ma = *reinterpret_cast<const ulonglong2*>(&msD[c * 64 + tb * 8]);
        const ulonglong2 mb = *reinterpret_cast<const ulonglong2*>(&msD[c * 64 + tb * 8 + 4]);
        hacc[0][0] = ffma2(ma.x, dot[0][0], hacc[0][0]);
        hacc[0][1] = ffma2(ma.x, dot[0][1], hacc[0][1]);
        hacc[1][0] = ffma2(ma.y, dot[1][0], hacc[1][0]);
        hacc[1][1] = ffma2(ma.y, dot[1][1], hacc[1][1]);
        hacc[2][0] = ffma2(mb.x, dot[2][0], hacc[2][0]);
        hacc[2][1] = ffma2(mb.x, dot[2][1], hacc[2][1]);
        hacc[3][0] = ffma2(mb.y, dot[3][0], hacc[3][0]);
        hacc[3][1] = ffma2(mb.y, dot[3][1], hacc[3][1]);
    }

    // ---- write partials: hPart[cg][h][b] ----
#pragma unroll
    for (int b = 0; b < 4; b++) {
#pragma unroll
        for (int hp = 0; hp < 2; hp++) {
            const float2 v = unpk(hacc[b][hp]);
            const int h0 = tg * 4 + hp * 2;
            const int bi = tb * 4 + b;
            hPart[cg * 1280 + h0 * 32 + bi]       = v.x;
            hPart[cg * 1280 + (h0 + 1) * 32 + bi] = v.y;
        }
    }
    __syncthreads();

    // ---- merge partials into duplicated hTd[h][2b] ----
    for (int idx = t; idx < N_HID * BT; idx += NTHR) {
        const int h = idx / BT;
        const int b = idx % BT;
        const float s = hPart[h * 32 + b] + hPart[1280 + h * 32 + b];
        hTd[h * 64 + 2 * b]     = s;
        hTd[h * 64 + 2 * b + 1] = s;
    }
    __syncthreads();

    // ================= Phase B: partial out over this cg's 20 c's ============
    // acc pairs: [4 batches][5 f-pairs], packed over adjacent f; thread f-pairs:
    // f = tg*2 + 20k + {0,1}, k = 0..4
    ull oacc[4][5];
#pragma unroll
    for (int b = 0; b < 4; b++)
#pragma unroll
        for (int k = 0; k < 5; k++) oacc[b][k] = 0ull;

    for (int cc = 0; cc < 20; cc++) {
        const int c = c0 + cc;
        const ulonglong2 ma = *reinterpret_cast<const ulonglong2*>(&msD[c * 64 + tb * 8]);
        const ulonglong2 mb = *reinterpret_cast<const ulonglong2*>(&msD[c * 64 + tb * 8 + 4]);
        const float* Gtc = Gtbase + (size_t)c * (N_HID * N_FEAT);

#pragma unroll 2
        for (int h = 0; h < N_HID; h++) {
            const ulonglong2 ha = *reinterpret_cast<const ulonglong2*>(&hTd[h * 64 + tb * 8]);
            const ulonglong2 hb = *reinterpret_cast<const ulonglong2*>(&hTd[h * 64 + tb * 8 + 4]);
            ull hm[4];
            hm[0] = fmul2(ma.x, ha.x);
            hm[1] = fmul2(ma.y, ha.y);
            hm[2] = fmul2(mb.x, hb.x);
            hm[3] = fmul2(mb.y, hb.y);
            const float* Gtrow = Gtc + h * N_FEAT + tg * 2;
#pragma unroll
            for (int k = 0; k < 5; k++) {
                const ull g = *reinterpret_cast<const ull*>(Gtrow + 20 * k);
                oacc[0][k] = ffma2(hm[0], g, oacc[0][k]);
                oacc[1][k] = ffma2(hm[1], g, oacc[1][k]);
                oacc[2][k] = ffma2(hm[2], g, oacc[2][k]);
                oacc[3][k] = ffma2(hm[3], g, oacc[3][k]);
            }
        }
    }

    // ---- cross-cg reduce + epilogue. cg1 stashes partials in xsD scratch ----
    float* osc = xsD;   // 32*100 = 3200 floats, xsD no longer needed
    if (cg == 1) {
#pragma unroll
        for (int b = 0; b < 4; b++) {
            const int bi = tb * 4 + b;
#pragma unroll
            for (int k = 0; k < 5; k++) {
                const float2 v = unpk(oacc[b][k]);
                const int f0 = tg * 2 + 20 * k;
                osc[bi * 100 + f0]     = v.x;
                osc[bi * 100 + f0 + 1] = v.y;
            }
        }
    }
    __syncthreads();
    if (cg == 0) {
#pragma unroll
        for (int k = 0; k < 5; k++) {
            const int f0 = tg * 2 + 20 * k;
            const float2 bf = *reinterpret_cast<const float2*>(&bfin[i * N_FEAT + f0]);
#pragma unroll
            for (int b = 0; b < 4; b++) {
                const int bi = tb * 4 + b;
                const float2 v = unpk(oacc[b][k]);
                const float r0 = v.x + osc[bi * 100 + f0]     + bf.x;
                const float r1 = v.y + osc[bi * 100 + f0 + 1] + bf.y;
                const size_t orow = ((size_t)(b0 + bi) * N_INST + i) * N_FEAT;
                out[orow + f0]     = fmaxf(r0, 0.f);
                out[orow + f0 + 1] = fmaxf(r1, 0.f);
            }
        }
    }
}

// ---------------------------------------------------------------------------
extern "C" void kernel_launch(void* const* d_in, const int* in_sizes, int n_in,
                              void* d_out, int out_size) {
    (void)in_sizes; (void)n_in; (void)out_size;
    const float* x    = (const float*)d_in[0];
    const float* mask = (const float*)d_in[1];
    const float* A    = (const float*)d_in[2];
    const float* Bp   = (const float*)d_in[3];
    const float* bfin = (const float*)d_in[4];
    float* out = (float*)d_out;

    const int smem_bytes = 14080 * 4;
    cudaFuncSetAttribute(tmsspd_main_kernel,
                         cudaFuncAttributeMaxDynamicSharedMemorySize, smem_bytes);

    compute_G_kernel<<<N_INST * NC, 128>>>(A, Bp);

    dim3 grid(B_SZ / BT, N_INST);
    tmsspd_main_kernel<<<grid, NTHR, smem_bytes>>>(x, mask, bfin, out);
}

// round 3
// speedup vs baseline: 2.0931x; 2.0931x over previous
#include <cuda_runtime.h>

typedef unsigned long long ull;

#define B_SZ   2048
#define N_INST 8
#define N_FEAT 100
#define N_HID  40
#define NC     40
#define NM     41

#define BT     32
#define NTHR   256

#define FPAD   104                      // padded f-dim for Gt rows
#define CSTRIDE_A  4000                 // floats per c, phase A layout [f][40]
#define CSTRIDE_B  (N_HID * FPAD)       // 4160 floats per c, phase B layout [h][104]
#define STAGE_FLTS 8320                 // max(2*4000, 2*4160)

// Precomputed G (two layouts). L2-resident.
__device__ float g_G  [N_INST * NC * N_FEAT * N_HID];     // [ic][f][h]
__device__ float g_Gt2[N_INST * NC * N_HID * FPAD];       // [ic][h][104] (f-padded w/ zeros)

// ---- packed fp32x2 (Blackwell FFMA2, PTX-only) ----
__device__ __forceinline__ ull ffma2(ull a, ull b, ull c) {
    ull d; asm("fma.rn.f32x2 %0, %1, %2, %3;" : "=l"(d) : "l"(a), "l"(b), "l"(c)); return d;
}
__device__ __forceinline__ ull pack2(float a, float b) {
    ull d; asm("mov.b64 %0, {%1, %2};" : "=l"(d) : "f"(a), "f"(b)); return d;
}
__device__ __forceinline__ float2 unpk(ull v) {
    float2 r; asm("mov.b64 {%0, %1}, %2;" : "=f"(r.x), "=f"(r.y) : "l"(v)); return r;
}

// ---- cp.async helpers ----
__device__ __forceinline__ void cp16(void* smem_dst, const void* gmem_src) {
    unsigned s = (unsigned)__cvta_generic_to_shared(smem_dst);
    asm volatile("cp.async.cg.shared.global [%0], [%1], 16;" :: "r"(s), "l"(gmem_src) : "memory");
}
__device__ __forceinline__ void cp_commit() { asm volatile("cp.async.commit_group;" ::: "memory"); }
__device__ __forceinline__ void cp_wait1()  { asm volatile("cp.async.wait_group 1;" ::: "memory"); }
__device__ __forceinline__ void cp_wait0()  { asm volatile("cp.async.wait_group 0;" ::: "memory"); }

__device__ __forceinline__ void stage(float* dst, const float* src, int n16, int t) {
    for (int idx = t; idx < n16; idx += NTHR)
        cp16((char*)dst + idx * 16, (const char*)src + idx * 16);
}

// ---------------------------------------------------------------------------
// Kernel 1: G = A @ Bp per (i,c); write [f][h] and padded-transposed [h][104]
// ---------------------------------------------------------------------------
__global__ void compute_G_kernel(const float* __restrict__ A,
                                 const float* __restrict__ Bp) {
    __shared__ float As[N_FEAT * NM];
    __shared__ float Bs[NM * N_HID];
    const int ic = blockIdx.x;
    const float* Ap  = A  + (size_t)ic * N_FEAT * NM;
    const float* Bpp = Bp + (size_t)ic * NM * N_HID;
    for (int idx = threadIdx.x; idx < N_FEAT * NM; idx += blockDim.x) As[idx] = Ap[idx];
    for (int idx = threadIdx.x; idx < NM * N_HID; idx += blockDim.x) Bs[idx] = Bpp[idx];
    // zero pad cols of Gt2
    for (int idx = threadIdx.x; idx < N_HID * 4; idx += blockDim.x) {
        const int h = idx >> 2, fp = N_FEAT + (idx & 3);
        g_Gt2[(size_t)ic * CSTRIDE_B + h * FPAD + fp] = 0.f;
    }
    __syncthreads();
    for (int idx = threadIdx.x; idx < N_FEAT * N_HID; idx += blockDim.x) {
        const int f = idx / N_HID, h = idx % N_HID;
        float s = 0.f;
#pragma unroll
        for (int m = 0; m < NM; m++) s += As[f * NM + m] * Bs[m * N_HID + h];
        g_G  [(size_t)ic * CSTRIDE_A + f * N_HID + h] = s;
        g_Gt2[(size_t)ic * CSTRIDE_B + h * FPAD + f] = s;
    }
}

// ---------------------------------------------------------------------------
// Kernel 2: fused, lane = batch, warp-uniform G broadcast, cp.async double buf.
// SMEM (floats):
//   Gs    [2][8320]  16640   staged G (A) / Gt (B); aliased as out-stash later
//   xsT   [100][32]   3200
//   msT   [ 40][32]   1280
//   hPart [4][40][32] 5120
//   hT    [40][32]    1280
// total 27520 floats = 110080 B
// ---------------------------------------------------------------------------
__global__ __launch_bounds__(NTHR, 2)
void tmsspd_main_kernel(const float* __restrict__ x,
                        const float* __restrict__ mask,
                        const float* __restrict__ bfin,
                        float* __restrict__ out) {
    extern __shared__ float sm[];
    float* Gs    = sm;            // 16640
    float* xsT   = sm + 16640;    // 3200
    float* msT   = sm + 19840;    // 1280
    float* hPart = sm + 21120;    // 5120
    float* hT    = sm + 26240;    // 1280

    const int i    = blockIdx.y;
    const int b0   = blockIdx.x * BT;
    const int t    = threadIdx.x;
    const int w    = t >> 5;
    const int lane = t & 31;

    const float* GA = g_G   + (size_t)i * NC * CSTRIDE_A;
    const float* GB = g_Gt2 + (size_t)i * NC * CSTRIDE_B;

    // prologue: phase-A stages 0,1 in flight ASAP
    stage(Gs,        GA,             2 * CSTRIDE_A / 4, t); cp_commit();
    stage(Gs + STAGE_FLTS, GA + 2 * CSTRIDE_A, 2 * CSTRIDE_A / 4, t); cp_commit();

    // x, mask tiles (transposed: [f][b], [c][b])
    for (int idx = t; idx < BT * N_FEAT; idx += NTHR) {
        const int bl = idx / N_FEAT, f = idx % N_FEAT;
        xsT[f * BT + bl] = x[((size_t)(b0 + bl) * N_INST + i) * N_FEAT + f];
    }
    for (int idx = t; idx < BT * NC; idx += NTHR) {
        const int bl = idx / NC, c = idx % NC;
        msT[c * BT + bl] = mask[((size_t)(b0 + bl) * N_INST + i) * NC + c];
    }

    // ================= Phase A =================
    // warp roles: hg = w&1 (h-half of 20), cp = (w>>1)&1 (c parity), fs = w>>2 (f half of 50)
    {
        const int hg = w & 1, cp = (w >> 1) & 1, fs = w >> 2;
        ull hacc[10];
#pragma unroll
        for (int j = 0; j < 10; j++) hacc[j] = 0ull;

        for (int k = 0; k < 20; k++) {
            if (k < 19) cp_wait1(); else cp_wait0();
            __syncthreads();

            const float* Gc = Gs + (k & 1) * STAGE_FLTS + cp * CSTRIDE_A;
            const int c = 2 * k + cp;
            const float m = msT[c * BT + lane];
            const int f0 = fs * 50;
#pragma unroll 2
            for (int ff = 0; ff < 50; ff++) {
                const int f = f0 + ff;
                const float xm = xsT[f * BT + lane] * m;
                const ull xmd = pack2(xm, xm);
                const ulonglong2* Grow =
                    reinterpret_cast<const ulonglong2*>(Gc + f * N_HID + hg * 20);
#pragma unroll
                for (int j = 0; j < 5; j++) {
                    const ulonglong2 g = Grow[j];
                    hacc[2 * j]     = ffma2(xmd, g.x, hacc[2 * j]);
                    hacc[2 * j + 1] = ffma2(xmd, g.y, hacc[2 * j + 1]);
                }
            }
            __syncthreads();
            if (k + 2 <= 19) {
                stage(Gs + (k & 1) * STAGE_FLTS, GA + (size_t)(2 * k + 4) * CSTRIDE_A,
                      2 * CSTRIDE_A / 4, t);
                cp_commit();
            }
        }

        // first phase-B stage can start now (buf0 free)
        stage(Gs, GB, 2 * CSTRIDE_B / 4, t); cp_commit();

        // partials -> hPart[cp + 2*fs][h][b]
        const int p = cp + 2 * fs;
#pragma unroll
        for (int j = 0; j < 10; j++) {
            const float2 v = unpk(hacc[j]);
            const int h = hg * 20 + 2 * j;
            hPart[p * 1280 + h * BT + lane]       = v.x;
            hPart[p * 1280 + (h + 1) * BT + lane] = v.y;
        }
    }
    __syncthreads();

    // merge h
    for (int idx = t; idx < N_HID * BT; idx += NTHR)
        hT[idx] = hPart[idx] + hPart[1280 + idx] + hPart[2560 + idx] + hPart[3840 + idx];

    // second phase-B stage (buf1 free)
    stage(Gs + STAGE_FLTS, GB + 2 * CSTRIDE_B, 2 * CSTRIDE_B / 4, t); cp_commit();
    __syncthreads();

    // ================= Phase B =================
    // warp roles: fq = w&3 (f chunks at 0/28/56/84, sizes 28/28/28/20), hh2 = w>>2 (h half)
    const int fq = w & 3, hh2 = w >> 2;
    const int f0 = fq * 28;
    const int NP = (fq == 3) ? 5 : 7;       // ulonglong2 loads per row
    ull oacc[14];
#pragma unroll
    for (int j = 0; j < 14; j++) oacc[j] = 0ull;

    for (int k = 0; k < 20; k++) {
        if (k < 19) cp_wait1(); else cp_wait0();
        __syncthreads();

        const float* Gb = Gs + (k & 1) * STAGE_FLTS;
#pragma unroll
        for (int cpi = 0; cpi < 2; cpi++) {
            const int c = 2 * k + cpi;
            const float m = msT[c * BT + lane];
            const float* Gc = Gb + cpi * CSTRIDE_B;
#pragma unroll 2
            for (int hh = 0; hh < 20; hh++) {
                const int h = hh2 * 20 + hh;
                const float hm = hT[h * BT + lane] * m;
                const ull hmd = pack2(hm, hm);
                const ulonglong2* Grow =
                    reinterpret_cast<const ulonglong2*>(Gc + h * FPAD + f0);
                if (NP == 7) {
#pragma unroll
                    for (int j = 0; j < 7; j++) {
                        const ulonglong2 g = Grow[j];
                        oacc[2 * j]     = ffma2(hmd, g.x, oacc[2 * j]);
                        oacc[2 * j + 1] = ffma2(hmd, g.y, oacc[2 * j + 1]);
                    }
                } else {
#pragma unroll
                    for (int j = 0; j < 5; j++) {
                        const ulonglong2 g = Grow[j];
                        oacc[2 * j]     = ffma2(hmd, g.x, oacc[2 * j]);
                        oacc[2 * j + 1] = ffma2(hmd, g.y, oacc[2 * j + 1]);
                    }
                }
            }
        }
        __syncthreads();
        if (k + 2 <= 19) {
            stage(Gs + (k & 1) * STAGE_FLTS, GB + (size_t)(2 * k + 4) * CSTRIDE_B,
                  2 * CSTRIDE_B / 4, t);
            cp_commit();
        }
    }

    // cross-half reduce + epilogue; stash in Gs (dead now)
    float* stash = Gs;   // [32][104]
    if (hh2 == 1) {
        const int np2 = 2 * NP;
#pragma unroll
        for (int p = 0; p < 14; p++) {
            if (p >= np2) break;
            const float2 v = unpk(oacc[p]);
            *reinterpret_cast<float2*>(&stash[lane * FPAD + f0 + 2 * p]) = v;
        }
    }
    __syncthreads();
    if (hh2 == 0) {
        const size_t orow = ((size_t)(b0 + lane) * N_INST + i) * N_FEAT;
        const int np2 = 2 * NP;
#pragma unroll
        for (int p = 0; p < 14; p++) {
            if (p >= np2) break;
            const int f = f0 + 2 * p;
            if (f >= N_FEAT) break;
            const float2 v  = unpk(oacc[p]);
            const float2 s2 = *reinterpret_cast<const float2*>(&stash[lane * FPAD + f]);
            const float2 bf = *reinterpret_cast<const float2*>(&bfin[i * N_FEAT + f]);
            float2 r;
            r.x = fmaxf(v.x + s2.x + bf.x, 0.f);
            r.y = fmaxf(v.y + s2.y + bf.y, 0.f);
            *reinterpret_cast<float2*>(&out[orow + f]) = r;
        }
    }
}

// ---------------------------------------------------------------------------
extern "C" void kernel_launch(void* const* d_in, const int* in_sizes, int n_in,
                              void* d_out, int out_size) {
    (void)in_sizes; (void)n_in; (void)out_size;
    const float* x    = (const float*)d_in[0];
    const float* mask = (const float*)d_in[1];
    const float* A    = (const float*)d_in[2];
    const float* Bp   = (const float*)d_in[3];
    const float* bfin = (const float*)d_in[4];
    float* out = (float*)d_out;

    const int smem_bytes = 27520 * 4;   // 110080
    cudaFuncSetAttribute(tmsspd_main_kernel,
                         cudaFuncAttributeMaxDynamicSharedMemorySize, smem_bytes);

    compute_G_kernel<<<N_INST * NC, 128>>>(A, Bp);

    dim3 grid(B_SZ / BT, N_INST);
    tmsspd_main_kernel<<<grid, NTHR, smem_bytes>>>(x, mask, bfin, out);
}

// round 4
// speedup vs baseline: 2.7756x; 1.3261x over previous
#include <cuda_runtime.h>

typedef unsigned long long ull;

#define B_SZ   2048
#define N_INST 8
#define N_FEAT 100
#define N_HID  40
#define NC     40
#define NM     41

#define BT     32
#define NTHR   256

#define GA_C   4800            // floats per c, phase A staged: [f][48] (h in 4 slots of 12, 10 used)
#define GB_C   4480            // floats per c, phase B staged: [h][112] (f in 4 slots of 28, 26 used)
#define BUFSZ  4800            // ring slot size (max of the two)

// Precomputed G in both staged layouts (L2-resident, ~12 MB total)
__device__ float g_GA[N_INST * NC * GA_C];
__device__ float g_GB[N_INST * NC * GB_C];

// ---- packed fp32x2 (Blackwell FFMA2, PTX-only) ----
__device__ __forceinline__ ull ffma2(ull a, ull b, ull c) {
    ull d; asm("fma.rn.f32x2 %0, %1, %2, %3;" : "=l"(d) : "l"(a), "l"(b), "l"(c)); return d;
}
__device__ __forceinline__ ull fmul2(ull a, ull b) {
    ull d; asm("mul.rn.f32x2 %0, %1, %2;" : "=l"(d) : "l"(a), "l"(b)); return d;
}
__device__ __forceinline__ ull pack2(float a, float b) {
    ull d; asm("mov.b64 %0, {%1, %2};" : "=l"(d) : "f"(a), "f"(b)); return d;
}
__device__ __forceinline__ float2 unpk(ull v) {
    float2 r; asm("mov.b64 {%0, %1}, %2;" : "=f"(r.x), "=f"(r.y) : "l"(v)); return r;
}

// ---- cp.async ----
__device__ __forceinline__ void cp16(void* smem_dst, const void* gmem_src) {
    unsigned s = (unsigned)__cvta_generic_to_shared(smem_dst);
    asm volatile("cp.async.cg.shared.global [%0], [%1], 16;" :: "r"(s), "l"(gmem_src) : "memory");
}
__device__ __forceinline__ void cp_commit() { asm volatile("cp.async.commit_group;" ::: "memory"); }
__device__ __forceinline__ void cp_waitn(int n) {
    if (n <= 0)      asm volatile("cp.async.wait_group 0;" ::: "memory");
    else if (n == 1) asm volatile("cp.async.wait_group 1;" ::: "memory");
    else             asm volatile("cp.async.wait_group 2;" ::: "memory");
}
__device__ __forceinline__ void stage(float* dst, const float* src, int n16, int t) {
    for (int idx = t; idx < n16; idx += NTHR)
        cp16((char*)dst + idx * 16, (const char*)src + idx * 16);
}

// ---------------------------------------------------------------------------
// Kernel 1: G = A @ Bp per (i,c), written into both staged layouts.
// ---------------------------------------------------------------------------
__global__ void compute_G_kernel(const float* __restrict__ A,
                                 const float* __restrict__ Bp) {
    __shared__ float As[N_FEAT * NM];
    __shared__ float Bs[NM * N_HID];
    const int ic = blockIdx.x;
    const float* Ap  = A  + (size_t)ic * N_FEAT * NM;
    const float* Bpp = Bp + (size_t)ic * NM * N_HID;
    float* GAo = g_GA + (size_t)ic * GA_C;
    float* GBo = g_GB + (size_t)ic * GB_C;

    for (int idx = threadIdx.x; idx < N_FEAT * NM; idx += blockDim.x) As[idx] = Ap[idx];
    for (int idx = threadIdx.x; idx < NM * N_HID; idx += blockDim.x) Bs[idx] = Bpp[idx];
    // zero pad slots
    for (int idx = threadIdx.x; idx < N_FEAT * 8; idx += blockDim.x) {
        const int f = idx >> 3, k = idx & 7;           // lh = k/2, slot 10/11
        GAo[f * 48 + (k >> 1) * 12 + 10 + (k & 1)] = 0.f;
    }
    for (int idx = threadIdx.x; idx < N_HID * 12; idx += blockDim.x) {
        const int h = idx / 12, k = idx % 12;
        int col = (k < 6) ? ((k >> 1) * 28 + 26 + (k & 1)) : (106 + (k - 6));
        GBo[h * 112 + col] = 0.f;
    }
    __syncthreads();
    for (int idx = threadIdx.x; idx < N_FEAT * N_HID; idx += blockDim.x) {
        const int f = idx / N_HID, h = idx % N_HID;
        float s = 0.f;
#pragma unroll
        for (int m = 0; m < NM; m++) s += As[f * NM + m] * Bs[m * N_HID + h];
        GAo[f * 48 + (h / 10) * 12 + (h % 10)] = s;          // A layout
        GBo[h * 112 + (f / 26) * 28 + (f % 26)] = s;          // B layout (f remapped)
    }
}

// ---------------------------------------------------------------------------
// Kernel 2. SMEM (floats):
//   S0    [3][4800] 14400  G ring (A/B); epilogue: P1/P2 stash (2x3328)
//   xs    [100][32]  3200
//   ms    [ 40][32]  1280
//   hPart [4][40][32] 5120
//   hT    [40][32]   1280
// total 25280 floats = 101120 B -> 2 CTAs/SM
// ---------------------------------------------------------------------------
__global__ __launch_bounds__(NTHR, 2)
void tmsspd_main_kernel(const float* __restrict__ x,
                        const float* __restrict__ mask,
                        const float* __restrict__ bfin,
                        float* __restrict__ out) {
    extern __shared__ float sm[];
    float* S0    = sm;            // 14400
    float* xs    = sm + 14400;    // 3200
    float* ms    = sm + 17600;    // 1280
    float* hPart = sm + 18880;    // 5120
    float* hT    = sm + 24000;    // 1280

    const int i    = blockIdx.y;
    const int b0   = blockIdx.x * BT;
    const int t    = threadIdx.x;
    const int w    = t >> 5;
    const int lane = t & 31;
    const int lb   = lane & 7;    // 8 b-groups (2 b each within the warp's 16-b half)
    const int lh   = lane >> 3;   // 4 slot-groups

    const float* GAsrc = g_GA + (size_t)i * NC * GA_C;
    const float* GBsrc = g_GB + (size_t)i * NC * GB_C;

    // prologue: stage c=0,1 for phase A
    stage(S0,          GAsrc,        GA_C / 4, t); cp_commit();
    stage(S0 + BUFSZ,  GAsrc + GA_C, GA_C / 4, t); cp_commit();

    // load x, mask tiles (transposed [f][b], [c][b])
    for (int idx = t; idx < BT * N_FEAT; idx += NTHR) {
        const int bl = idx / N_FEAT, f = idx % N_FEAT;
        xs[f * BT + bl] = x[((size_t)(b0 + bl) * N_INST + i) * N_FEAT + f];
    }
    for (int idx = t; idx < BT * NC; idx += NTHR) {
        const int bl = idx / NC, c = idx % NC;
        ms[c * BT + bl] = mask[((size_t)(b0 + bl) * N_INST + i) * NC + c];
    }

    // ======================= Phase A =======================
    // warp: bq = w&1 (16-b half), fq = w>>1 (25-f slice)
    // thread: b = bq*16 + lb*2 + {0,1};  h = lh*10 + 0..9 (5 h-pairs)
    {
        const int bq = w & 1, fq = w >> 1;
        const int bb = bq * 16 + lb * 2;
        const int f0 = fq * 25;

        ull acc[2][5];
#pragma unroll
        for (int b = 0; b < 2; b++)
#pragma unroll
            for (int p = 0; p < 5; p++) acc[b][p] = 0ull;

        for (int c = 0; c < NC; c++) {
            __syncthreads();                       // compute c-1 done everywhere
            if (c + 2 < NC) {                      // stage c+2 into free buffer
                stage(S0 + ((c + 2) % 3) * BUFSZ, GAsrc + (size_t)(c + 2) * GA_C,
                      GA_C / 4, t);
                cp_commit();
            }
            cp_waitn(NC - 1 - c >= 2 ? 2 : NC - 1 - c);
            __syncthreads();                       // buffer c visible to all

            const float* Gc = S0 + (c % 3) * BUFSZ;
            const float2 mv = *reinterpret_cast<const float2*>(&ms[c * BT + bb]);
            const ull mpk = pack2(mv.x, mv.y);

#pragma unroll 5
            for (int ff = 0; ff < 25; ff++) {
                const int f = f0 + ff;
                const float2 xv = *reinterpret_cast<const float2*>(&xs[f * BT + bb]);
                const ull xm = fmul2(pack2(xv.x, xv.y), mpk);
                const float2 xf = unpk(xm);
                const ull xd0 = pack2(xf.x, xf.x);
                const ull xd1 = pack2(xf.y, xf.y);

                const float* gp = Gc + f * 48 + lh * 12;
                const ulonglong2 gA = *reinterpret_cast<const ulonglong2*>(gp);
                const ulonglong2 gB = *reinterpret_cast<const ulonglong2*>(gp + 4);
                const ull        gC = *reinterpret_cast<const ull*>(gp + 8);

                acc[0][0] = ffma2(xd0, gA.x, acc[0][0]);
                acc[0][1] = ffma2(xd0, gA.y, acc[0][1]);
                acc[0][2] = ffma2(xd0, gB.x, acc[0][2]);
                acc[0][3] = ffma2(xd0, gB.y, acc[0][3]);
                acc[0][4] = ffma2(xd0, gC,   acc[0][4]);
                acc[1][0] = ffma2(xd1, gA.x, acc[1][0]);
                acc[1][1] = ffma2(xd1, gA.y, acc[1][1]);
                acc[1][2] = ffma2(xd1, gB.x, acc[1][2]);
                acc[1][3] = ffma2(xd1, gB.y, acc[1][3]);
                acc[1][4] = ffma2(xd1, gC,   acc[1][4]);
            }
        }

        // partials: hPart[fq][h][b]
#pragma unroll
        for (int b = 0; b < 2; b++)
#pragma unroll
            for (int p = 0; p < 5; p++) {
                const float2 v = unpk(acc[b][p]);
                const int h = lh * 10 + 2 * p;
                hPart[fq * 1280 + h * BT + bb + b]       = v.x;
                hPart[fq * 1280 + (h + 1) * BT + bb + b] = v.y;
            }
    }
    __syncthreads();

    // stage first two phase-B buffers (S0 free now), then merge hT
    stage(S0,         GBsrc,        GB_C / 4, t); cp_commit();
    stage(S0 + BUFSZ, GBsrc + GB_C, GB_C / 4, t); cp_commit();

    for (int idx = t; idx < N_HID * BT; idx += NTHR)
        hT[idx] = hPart[idx] + hPart[1280 + idx] + hPart[2560 + idx] + hPart[3840 + idx];

    // ======================= Phase B =======================
    // warp: bq = w&1 (16-b half), hq = w>>1 (10-h slice)
    // thread: b = bq*16 + lb*2 + {0,1}; f-slot = lh*28 (26 used -> real f = lh*26 + j)
    const int bq = w & 1, hq = w >> 1;
    const int bb = bq * 16 + lb * 2;
    const int h0 = hq * 10;

    ull acc[2][13];
#pragma unroll
    for (int b = 0; b < 2; b++)
#pragma unroll
        for (int p = 0; p < 13; p++) acc[b][p] = 0ull;

    for (int c = 0; c < NC; c++) {
        __syncthreads();
        if (c + 2 < NC) {
            stage(S0 + ((c + 2) % 3) * BUFSZ, GBsrc + (size_t)(c + 2) * GB_C,
                  GB_C / 4, t);
            cp_commit();
        }
        cp_waitn(NC - 1 - c >= 2 ? 2 : NC - 1 - c);
        __syncthreads();

        const float* Gc = S0 + (c % 3) * BUFSZ;
        const float2 mv = *reinterpret_cast<const float2*>(&ms[c * BT + bb]);
        const ull mpk = pack2(mv.x, mv.y);

#pragma unroll 2
        for (int hh = 0; hh < 10; hh++) {
            const int h = h0 + hh;
            const float2 hv = *reinterpret_cast<const float2*>(&hT[h * BT + bb]);
            const ull hm = fmul2(pack2(hv.x, hv.y), mpk);
            const float2 hf = unpk(hm);
            const ull hd0 = pack2(hf.x, hf.x);
            const ull hd1 = pack2(hf.y, hf.y);

            const float* gp = Gc + h * 112 + lh * 28;
            const ulonglong2 g0 = *reinterpret_cast<const ulonglong2*>(gp);
            const ulonglong2 g1 = *reinterpret_cast<const ulonglong2*>(gp + 4);
            const ulonglong2 g2 = *reinterpret_cast<const ulonglong2*>(gp + 8);
            const ulonglong2 g3 = *reinterpret_cast<const ulonglong2*>(gp + 12);
            const ulonglong2 g4 = *reinterpret_cast<const ulonglong2*>(gp + 16);
            const ulonglong2 g5 = *reinterpret_cast<const ulonglong2*>(gp + 20);
            const ull        g6 = *reinterpret_cast<const ull*>(gp + 24);

            acc[0][0]  = ffma2(hd0, g0.x, acc[0][0]);
            acc[0][1]  = ffma2(hd0, g0.y, acc[0][1]);
            acc[0][2]  = ffma2(hd0, g1.x, acc[0][2]);
            acc[0][3]  = ffma2(hd0, g1.y, acc[0][3]);
            acc[0][4]  = ffma2(hd0, g2.x, acc[0][4]);
            acc[0][5]  = ffma2(hd0, g2.y, acc[0][5]);
            acc[0][6]  = ffma2(hd0, g3.x, acc[0][6]);
            acc[0][7]  = ffma2(hd0, g3.y, acc[0][7]);
            acc[0][8]  = ffma2(hd0, g4.x, acc[0][8]);
            acc[0][9]  = ffma2(hd0, g4.y, acc[0][9]);
            acc[0][10] = ffma2(hd0, g5.x, acc[0][10]);
            acc[0][11] = ffma2(hd0, g5.y, acc[0][11]);
            acc[0][12] = ffma2(hd0, g6,   acc[0][12]);
            acc[1][0]  = ffma2(hd1, g0.x, acc[1][0]);
            acc[1][1]  = ffma2(hd1, g0.y, acc[1][1]);
            acc[1][2]  = ffma2(hd1, g1.x, acc[1][2]);
            acc[1][3]  = ffma2(hd1, g1.y, acc[1][3]);
            acc[1][4]  = ffma2(hd1, g2.x, acc[1][4]);
            acc[1][5]  = ffma2(hd1, g2.y, acc[1][5]);
            acc[1][6]  = ffma2(hd1, g3.x, acc[1][6]);
            acc[1][7]  = ffma2(hd1, g3.y, acc[1][7]);
            acc[1][8]  = ffma2(hd1, g4.x, acc[1][8]);
            acc[1][9]  = ffma2(hd1, g4.y, acc[1][9]);
            acc[1][10] = ffma2(hd1, g5.x, acc[1][10]);
            acc[1][11] = ffma2(hd1, g5.y, acc[1][11]);
            acc[1][12] = ffma2(hd1, g6,   acc[1][12]);
        }
    }

    // ---- cross-hq reduce (4 partials) + epilogue. S0 dead -> P1, P2 stash ----
    float* P1 = S0;           // [32][104]
    float* P2 = S0 + 3328;    // [32][104]
    const int fb = lh * 26;   // real f base for this lane

    __syncthreads();
    if (hq == 1 || hq == 3) {
        float* P = (hq == 1) ? P1 : P2;
#pragma unroll
        for (int b = 0; b < 2; b++)
#pragma unroll
            for (int p = 0; p < 13; p++) {
                const float2 v = unpk(acc[b][p]);
                *reinterpret_cast<float2*>(&P[(bb + b) * 104 + fb + 2 * p]) = v;
            }
    }
    __syncthreads();
    if (hq == 0) {
#pragma unroll
        for (int b = 0; b < 2; b++)
#pragma unroll
            for (int p = 0; p < 13; p++) {
                const float2 s = *reinterpret_cast<const float2*>(&P1[(bb + b) * 104 + fb + 2 * p]);
                acc[b][p] = ffma2(pack2(1.f, 1.f), acc[b][p], pack2(s.x, s.y));
            }
    } else if (hq == 2) {
#pragma unroll
        for (int b = 0; b < 2; b++)
#pragma unroll
            for (int p = 0; p < 13; p++) {
                const float2 s = *reinterpret_cast<const float2*>(&P2[(bb + b) * 104 + fb + 2 * p]);
                const float2 v = unpk(acc[b][p]);
                float2 r; r.x = v.x + s.x; r.y = v.y + s.y;
                *reinterpret_cast<float2*>(&P2[(bb + b) * 104 + fb + 2 * p]) = r;
            }
    }
    __syncthreads();
    if (hq == 0) {
#pragma unroll
        for (int b = 0; b < 2; b++) {
            const size_t orow = ((size_t)(b0 + bb + b) * N_INST + i) * N_FEAT;
#pragma unroll
            for (int p = 0; p < 13; p++) {
                const int f = fb + 2 * p;
                if (f >= N_FEAT) break;          // skip pad pairs (lh==3, p>=11)
                const float2 s  = *reinterpret_cast<const float2*>(&P2[(bb + b) * 104 + f]);
                const float2 bf = *reinterpret_cast<const float2*>(&bfin[i * N_FEAT + f]);
                const float2 v  = unpk(acc[b][p]);
                float2 r;
                r.x = fmaxf(v.x + s.x + bf.x, 0.f);
                r.y = fmaxf(v.y + s.y + bf.y, 0.f);
                *reinterpret_cast<float2*>(&out[orow + f]) = r;
            }
        }
    }
}

// ---------------------------------------------------------------------------
extern "C" void kernel_launch(void* const* d_in, const int* in_sizes, int n_in,
                              void* d_out, int out_size) {
    (void)in_sizes; (void)n_in; (void)out_size;
    const float* x    = (const float*)d_in[0];
    const float* mask = (const float*)d_in[1];
    const float* A    = (const float*)d_in[2];
    const float* Bp   = (const float*)d_in[3];
    const float* bfin = (const float*)d_in[4];
    float* out = (float*)d_out;

    const int smem_bytes = 25280 * 4;   // 101120
    cudaFuncSetAttribute(tmsspd_main_kernel,
                         cudaFuncAttributeMaxDynamicSharedMemorySize, smem_bytes);

    compute_G_kernel<<<N_INST * NC, 128>>>(A, Bp);

    dim3 grid(B_SZ / BT, N_INST);
    tmsspd_main_kernel<<<grid, NTHR, smem_bytes>>>(x, mask, bfin, out);
}